// round 13
// baseline (speedup 1.0000x reference)
#include <cuda_runtime.h>
#include <cuda_bf16.h>
#include <cstdint>

// RSA_layer: B=64, U=W=128.  out[b][u] = sum_j f[j][u]*softmax_j(s[j][u]),
//   s[j][v] = (f @ w_hi)[j][v] + (f[127].f[j]) * w_dot[v]
// HMMA bf16 3-term hi/lo split GEMM; B fragments via ldmatrix.x4 (not scalar LDS).
// d[j] fused into staging; softmax fused into GEMM epilogue; no-max softmax
// (|s| <~ 40); 2 barriers.  Grid: 64x2 = 128 CTAs, 512 threads.

#define THREADS 512

#define A_STRIDE_B 272   // 136 bf16/row; ldmatrix 8-lane phases conflict-free
#define B_STRIDE_B 272   // 68 words = 4 mod 32 -> conflict-free LDSM phases
#define FT_STRIDE  133   // floats (odd); scalar reads only

#define OFF_A_HI 0
#define OFF_A_LO (128 * A_STRIDE_B)                    // 34816
#define OFF_B_HI (2 * 128 * A_STRIDE_B)                // 69632
#define OFF_B_LO (OFF_B_HI + 64 * B_STRIDE_B)          // 87040
#define OFF_FT   (OFF_B_LO + 64 * B_STRIDE_B)          // 104448 (16B aligned)
#define OFF_DS   (OFF_FT + 64 * FT_STRIDE * 4)         // 138496 (16B aligned)
#define OFF_WDOT (OFF_DS + 512)                        // 139008
#define OFF_RED  (OFF_WDOT + 256)                      // 139264: se[4][64], o[4][64]
#define SMEM_BYTES (OFF_RED + 2048)                    // 141312

__device__ __forceinline__ uint32_t smem_u32(const void* p) {
    return (uint32_t)__cvta_generic_to_shared((void*)p);
}

__device__ __forceinline__ void ldmatrix_x4(uint32_t* a, uint32_t addr) {
    asm volatile("ldmatrix.sync.aligned.m8n8.x4.shared.b16 {%0,%1,%2,%3}, [%4];"
                 : "=r"(a[0]), "=r"(a[1]), "=r"(a[2]), "=r"(a[3]) : "r"(addr));
}

__device__ __forceinline__ void mma_16816(float* c, const uint32_t* a,
                                          uint32_t b0, uint32_t b1) {
    asm volatile(
        "mma.sync.aligned.m16n8k16.row.col.f32.bf16.bf16.f32 "
        "{%0,%1,%2,%3}, {%4,%5,%6,%7}, {%8,%9}, {%0,%1,%2,%3};"
        : "+f"(c[0]), "+f"(c[1]), "+f"(c[2]), "+f"(c[3])
        : "r"(a[0]), "r"(a[1]), "r"(a[2]), "r"(a[3]), "r"(b0), "r"(b1));
}

__device__ __forceinline__ uint32_t pack_bf2(__nv_bfloat16 a, __nv_bfloat16 b) {
    __nv_bfloat162 t; t.x = a; t.y = b;
    return *reinterpret_cast<uint32_t*>(&t);
}

__global__ __launch_bounds__(THREADS, 1)
void rsa_kernel(const float* __restrict__ input,
                const float* __restrict__ state,
                const float* __restrict__ w,
                float* __restrict__ out)
{
    extern __shared__ char sm[];
    float* fT     = (float*)(sm + OFF_FT);     // fT[ul][j] = f[j][v0+ul] (64 rows)
    float* d_s    = (float*)(sm + OFF_DS);     // d[128]
    float* wdot_s = (float*)(sm + OFF_WDOT);   // wdot[64]
    float* red    = (float*)(sm + OFF_RED);    // [0:256) se[g][v], [256:512) o[g][v]

    const int tid = threadIdx.x;
    const int wid = tid >> 5;
    const int lid = tid & 31;
    const int b   = blockIdx.x >> 1;
    const int v0  = (blockIdx.x & 1) * 64;
    const int hsel = v0 >> 6;                  // which lane-half owns fT rows

    const float* stateb = state + (size_t)b * 128 * 128;
    const float* inputb = input + b * 128;

    // ---- q = f[127] quad per lane (aligned LDG.128 + shfl shift) ----
    float q0, q1, q2, q3;
    {
        float4 s4 = *(const float4*)(stateb + 127 * 128 + 4 * lid);
        float nx = __shfl_down_sync(0xffffffffu, s4.x, 1);
        if (lid == 31) nx = inputb[127];
        q0 = s4.y; q1 = s4.z; q2 = s4.w; q3 = nx;
    }

    // ---- Phase 0a: stage A bf16 hi/lo + d[j] in-register + fT (own half) ----
    #pragma unroll
    for (int it = 0; it < 8; it++) {
        const int j = wid + it * 16;
        float4 s4 = *(const float4*)(stateb + j * 128 + 4 * lid);
        float nx = __shfl_down_sync(0xffffffffu, s4.x, 1);
        if (lid == 31) nx = inputb[j];
        float f0 = s4.y, f1 = s4.z, f2 = s4.w, f3 = nx;  // f[j][4lid..4lid+3]

        __nv_bfloat16 h0 = __float2bfloat16(f0), h1 = __float2bfloat16(f1);
        __nv_bfloat16 h2 = __float2bfloat16(f2), h3 = __float2bfloat16(f3);
        __nv_bfloat16 l0 = __float2bfloat16(f0 - __bfloat162float(h0));
        __nv_bfloat16 l1 = __float2bfloat16(f1 - __bfloat162float(h1));
        __nv_bfloat16 l2 = __float2bfloat16(f2 - __bfloat162float(h2));
        __nv_bfloat16 l3 = __float2bfloat16(f3 - __bfloat162float(h3));
        uint2 hv; hv.x = pack_bf2(h0, h1); hv.y = pack_bf2(h2, h3);
        uint2 lv; lv.x = pack_bf2(l0, l1); lv.y = pack_bf2(l2, l3);
        *(uint2*)(sm + OFF_A_HI + j * A_STRIDE_B + lid * 8) = hv;
        *(uint2*)(sm + OFF_A_LO + j * A_STRIDE_B + lid * 8) = lv;

        // d[j] partial: dot(f_quad, q_quad), warp reduce
        float p = f0 * q0;
        p = fmaf(f1, q1, p); p = fmaf(f2, q2, p); p = fmaf(f3, q3, p);
        p += __shfl_xor_sync(0xffffffffu, p, 16);
        p += __shfl_xor_sync(0xffffffffu, p, 8);
        p += __shfl_xor_sync(0xffffffffu, p, 4);
        p += __shfl_xor_sync(0xffffffffu, p, 2);
        p += __shfl_xor_sync(0xffffffffu, p, 1);
        if (lid == 0) d_s[j] = p;

        // fT rows for this CTA's u-window (16 owning lanes)
        if ((lid >> 4) == hsel) {
            int ul = 4 * (lid & 15);
            fT[ul * FT_STRIDE + j]       = f0;
            fT[(ul + 1) * FT_STRIDE + j] = f1;
            fT[(ul + 2) * FT_STRIDE + j] = f2;
            fT[(ul + 3) * FT_STRIDE + j] = f3;
        }
    }

    // ---- Phase 0b: stage Bt[v][u] = w[u][v0+v] bf16 hi/lo, LDG.128 ----
    #pragma unroll
    for (int p = tid; p < 128 * 16; p += THREADS) {
        int u = p >> 4, v4i = (p & 15) * 4;
        float4 wv4 = *(const float4*)(w + u * 128 + v0 + v4i);
        float wv[4] = {wv4.x, wv4.y, wv4.z, wv4.w};
        #pragma unroll
        for (int i = 0; i < 4; i++) {
            __nv_bfloat16 h = __float2bfloat16(wv[i]);
            __nv_bfloat16 l = __float2bfloat16(wv[i] - __bfloat162float(h));
            *(__nv_bfloat16*)(sm + OFF_B_HI + (v4i + i) * B_STRIDE_B + u * 2) = h;
            *(__nv_bfloat16*)(sm + OFF_B_LO + (v4i + i) * B_STRIDE_B + u * 2) = l;
        }
    }
    if (tid < 64) wdot_s[tid] = w[256 * 128 + v0 + tid];
    __syncthreads();

    // ---- GEMM: warp tile = 32 j x 16 v (2 m-tiles x 2 n-tiles), K=128, 3 splits.
    //      B fragments via ldmatrix.x4: r0,r1 = b0,b1 of k-step 2k2; r2,r3 = 2k2+1 ----
    const int wj = (wid & 3) * 32;          // j block (group g = wid&3)
    const int wv = (wid >> 2) * 16;         // local v block

    float acc[2][2][4];
    #pragma unroll
    for (int mt = 0; mt < 2; mt++)
        #pragma unroll
        for (int n = 0; n < 2; n++)
            #pragma unroll
            for (int c = 0; c < 4; c++) acc[mt][n][c] = 0.f;

    {
        const int lrow  = lid & 15;
        const int lcolb = (lid >> 4) * 16;
        const int bvrow = lid & 7;              // B n-row within block
        const int bcolb = (lid >> 3) * 16;      // 0,16,32,48: b0/b1 x 2 k-steps

        const uint32_t a_off[3] = {OFF_A_HI, OFF_A_LO, OFF_A_HI};
        const uint32_t b_off[3] = {OFF_B_HI, OFF_B_HI, OFF_B_LO};
        const uint32_t smb = smem_u32(sm);

        #pragma unroll
        for (int s = 0; s < 3; s++) {
            const uint32_t abase = smb + a_off[s]
                                 + (uint32_t)(wj + lrow) * A_STRIDE_B + lcolb;
            const uint32_t bbase0 = smb + b_off[s]
                                 + (uint32_t)(wv + bvrow) * B_STRIDE_B + bcolb;
            const uint32_t bbase1 = bbase0 + 8 * B_STRIDE_B;
            #pragma unroll
            for (int k2 = 0; k2 < 4; k2++) {
                uint32_t a00[4], a01[4], a10[4], a11[4];
                ldmatrix_x4(a00, abase + (2 * k2) * 32);
                ldmatrix_x4(a01, abase + (2 * k2 + 1) * 32);
                ldmatrix_x4(a10, abase + 16 * A_STRIDE_B + (2 * k2) * 32);
                ldmatrix_x4(a11, abase + 16 * A_STRIDE_B + (2 * k2 + 1) * 32);
                uint32_t b0[4], b1[4];
                ldmatrix_x4(b0, bbase0 + k2 * 64);
                ldmatrix_x4(b1, bbase1 + k2 * 64);
                mma_16816(acc[0][0], a00, b0[0], b0[1]);
                mma_16816(acc[1][0], a10, b0[0], b0[1]);
                mma_16816(acc[0][1], a00, b1[0], b1[1]);
                mma_16816(acc[1][1], a10, b1[0], b1[1]);
                mma_16816(acc[0][0], a01, b0[2], b0[3]);
                mma_16816(acc[1][0], a11, b0[2], b0[3]);
                mma_16816(acc[0][1], a01, b1[2], b1[3]);
                mma_16816(acc[1][1], a11, b1[2], b1[3]);
            }
        }
    }

    // ---- Fused epilogue: fold d*wdot, exp, weighted sums on fragments ----
    {
        const int er = lid >> 2;            // j row within tile
        const int ec = (lid & 3) * 2;       // v pair within tile

        float se[2][2] = {{0.f, 0.f}, {0.f, 0.f}};   // [n][v-pair elem]
        float oo[2][2] = {{0.f, 0.f}, {0.f, 0.f}};

        #pragma unroll
        for (int mt = 0; mt < 2; mt++) {
            int j0 = wj + mt * 16 + er, j8 = j0 + 8;
            float d0 = d_s[j0], d8 = d_s[j8];
            #pragma unroll
            for (int n = 0; n < 2; n++) {
                int v = wv + n * 8 + ec;
                float wd0 = wdot_s[v], wd1 = wdot_s[v + 1];
                float e00 = __expf(fmaf(d0, wd0, acc[mt][n][0]));
                float e01 = __expf(fmaf(d0, wd1, acc[mt][n][1]));
                float e10 = __expf(fmaf(d8, wd0, acc[mt][n][2]));
                float e11 = __expf(fmaf(d8, wd1, acc[mt][n][3]));
                se[n][0] += e00 + e10;
                se[n][1] += e01 + e11;
                oo[n][0] = fmaf(e00, fT[v * FT_STRIDE + j0], oo[n][0]);
                oo[n][0] = fmaf(e10, fT[v * FT_STRIDE + j8], oo[n][0]);
                oo[n][1] = fmaf(e01, fT[(v + 1) * FT_STRIDE + j0], oo[n][1]);
                oo[n][1] = fmaf(e11, fT[(v + 1) * FT_STRIDE + j8], oo[n][1]);
            }
        }

        // reduce over the 8 er-lanes (lid bits 2..4)
        #pragma unroll
        for (int n = 0; n < 2; n++)
            #pragma unroll
            for (int c = 0; c < 2; c++) {
                se[n][c] += __shfl_xor_sync(0xffffffffu, se[n][c], 4);
                se[n][c] += __shfl_xor_sync(0xffffffffu, se[n][c], 8);
                se[n][c] += __shfl_xor_sync(0xffffffffu, se[n][c], 16);
                oo[n][c] += __shfl_xor_sync(0xffffffffu, oo[n][c], 4);
                oo[n][c] += __shfl_xor_sync(0xffffffffu, oo[n][c], 8);
                oo[n][c] += __shfl_xor_sync(0xffffffffu, oo[n][c], 16);
            }

        // lanes 0..3 deposit partials for this warp's j-group g = wid&3
        if (lid < 4) {
            const int g = wid & 3;
            #pragma unroll
            for (int n = 0; n < 2; n++) {
                int v = wv + n * 8 + ec;    // ec = 2*lid here
                red[g * 64 + v]           = se[n][0];
                red[g * 64 + v + 1]       = se[n][1];
                red[256 + g * 64 + v]     = oo[n][0];
                red[256 + g * 64 + v + 1] = oo[n][1];
            }
        }
    }
    __syncthreads();

    // ---- Final: sum 4 j-group partials, divide, store ----
    if (tid < 64) {
        float se = (red[tid] + red[64 + tid]) + (red[128 + tid] + red[192 + tid]);
        float o  = (red[256 + tid] + red[320 + tid]) + (red[384 + tid] + red[448 + tid]);
        out[b * 128 + v0 + tid] = __fdividef(o, se);
    }
}

extern "C" void kernel_launch(void* const* d_in, const int* in_sizes, int n_in,
                              void* d_out, int out_size)
{
    const float* input = (const float*)d_in[0];   // (64,128)
    const float* state = (const float*)d_in[1];   // (64,128,128)
    const float* w     = (const float*)d_in[2];   // (257,128); w[128:256], b unused
    float* out = (float*)d_out;                   // (64,128)

    cudaFuncSetAttribute(rsa_kernel,
                         cudaFuncAttributeMaxDynamicSharedMemorySize, SMEM_BYTES);
    rsa_kernel<<<128, THREADS, SMEM_BYTES>>>(input, state, w, out);
}

// round 14
// speedup vs baseline: 1.5685x; 1.5685x over previous
#include <cuda_runtime.h>
#include <cuda_bf16.h>
#include <cstdint>

// RSA_layer: B=64, U=W=128.  out[b][u] = sum_j f[j][u]*softmax_j(s[j][u]),
//   s[j][v] = f[j] . (w_hi[:,v] + wdot[v]*q)   with q = f[127]   (d-term folded
//   into B algebraically).  HMMA bf16 3-term hi/lo split GEMM; softmax fused
//   into the GEMM epilogue; no-max softmax (|s| <~ 40); 2 barriers.
// Grid: 64 batches x 2 v-halves = 128 CTAs, 512 threads (16 warps).

#define THREADS 512

#define A_STRIDE_B 272   // A row bytes (136 bf16): ldmatrix rows conflict-free
#define B_STRIDE_B 276   // Bt row bytes: conflict-free transpose stores
#define FT_STRIDE  133   // floats (odd); scalar reads only

#define OFF_A_HI 0
#define OFF_A_LO (128 * A_STRIDE_B)                    // 34816
#define OFF_B_HI (2 * 128 * A_STRIDE_B)                // 69632
#define OFF_B_LO (OFF_B_HI + 64 * B_STRIDE_B)          // 87296
#define OFF_FT   (OFF_B_LO + 64 * B_STRIDE_B)          // 104960 (16B aligned)
#define OFF_RED  (OFF_FT + 64 * FT_STRIDE * 4)         // 139008: se[4][64], o[4][64]
#define SMEM_BYTES (OFF_RED + 2048)                    // 141056

__device__ __forceinline__ uint32_t smem_u32(const void* p) {
    return (uint32_t)__cvta_generic_to_shared((void*)p);
}

__device__ __forceinline__ void ldmatrix_x4(uint32_t* a, uint32_t addr) {
    asm volatile("ldmatrix.sync.aligned.m8n8.x4.shared.b16 {%0,%1,%2,%3}, [%4];"
                 : "=r"(a[0]), "=r"(a[1]), "=r"(a[2]), "=r"(a[3]) : "r"(addr));
}

__device__ __forceinline__ void mma_16816(float* c, const uint32_t* a,
                                          uint32_t b0, uint32_t b1) {
    asm volatile(
        "mma.sync.aligned.m16n8k16.row.col.f32.bf16.bf16.f32 "
        "{%0,%1,%2,%3}, {%4,%5,%6,%7}, {%8,%9}, {%0,%1,%2,%3};"
        : "+f"(c[0]), "+f"(c[1]), "+f"(c[2]), "+f"(c[3])
        : "r"(a[0]), "r"(a[1]), "r"(a[2]), "r"(a[3]), "r"(b0), "r"(b1));
}

__device__ __forceinline__ uint32_t pack_bf2(__nv_bfloat16 a, __nv_bfloat16 b) {
    __nv_bfloat162 t; t.x = a; t.y = b;
    return *reinterpret_cast<uint32_t*>(&t);
}

__global__ __launch_bounds__(THREADS, 1)
void rsa_kernel(const float* __restrict__ input,
                const float* __restrict__ state,
                const float* __restrict__ w,
                float* __restrict__ out)
{
    extern __shared__ char sm[];
    float* fT  = (float*)(sm + OFF_FT);     // fT[ul][j] = f[j][v0+ul] (64 rows)
    float* red = (float*)(sm + OFF_RED);    // [0:256) se[g][v], [256:512) o[g][v]

    const int tid = threadIdx.x;
    const int wid = tid >> 5;
    const int lid = tid & 31;
    const int b   = blockIdx.x >> 1;
    const int v0  = (blockIdx.x & 1) * 64;
    const int hsel = v0 >> 6;                  // which lane-half owns fT rows

    const float* stateb = state + (size_t)b * 128 * 128;
    const float* inputb = input + b * 128;

    // ---- Phase 0a: stage A = f[j][u] bf16 hi/lo + fT fp32 (own half) ----
    #pragma unroll
    for (int it = 0; it < 8; it++) {
        const int j = wid + it * 16;
        float4 s4 = *(const float4*)(stateb + j * 128 + 4 * lid);
        float nx = __shfl_down_sync(0xffffffffu, s4.x, 1);
        if (lid == 31) nx = inputb[j];
        float f0 = s4.y, f1 = s4.z, f2 = s4.w, f3 = nx;  // f[j][4lid..4lid+3]

        __nv_bfloat16 h0 = __float2bfloat16(f0), h1 = __float2bfloat16(f1);
        __nv_bfloat16 h2 = __float2bfloat16(f2), h3 = __float2bfloat16(f3);
        __nv_bfloat16 l0 = __float2bfloat16(f0 - __bfloat162float(h0));
        __nv_bfloat16 l1 = __float2bfloat16(f1 - __bfloat162float(h1));
        __nv_bfloat16 l2 = __float2bfloat16(f2 - __bfloat162float(h2));
        __nv_bfloat16 l3 = __float2bfloat16(f3 - __bfloat162float(h3));
        uint2 hv; hv.x = pack_bf2(h0, h1); hv.y = pack_bf2(h2, h3);
        uint2 lv; lv.x = pack_bf2(l0, l1); lv.y = pack_bf2(l2, l3);
        *(uint2*)(sm + OFF_A_HI + j * A_STRIDE_B + lid * 8) = hv;
        *(uint2*)(sm + OFF_A_LO + j * A_STRIDE_B + lid * 8) = lv;

        // fT rows for this CTA's u-window (16 owning lanes)
        if ((lid >> 4) == hsel) {
            int ul = 4 * (lid & 15);
            fT[ul * FT_STRIDE + j]       = f0;
            fT[(ul + 1) * FT_STRIDE + j] = f1;
            fT[(ul + 2) * FT_STRIDE + j] = f2;
            fT[(ul + 3) * FT_STRIDE + j] = f3;
        }
    }

    // ---- Phase 0b: stage B' = w_hi[u][v0+v] + wdot[v]*q[u], bf16 hi/lo ----
    #pragma unroll
    for (int p = tid; p < 128 * 16; p += THREADS) {
        int u = p >> 4, v4i = (p & 15) * 4;
        float qu = (u < 127) ? stateb[127 * 128 + u + 1] : inputb[127];
        float4 wv4 = *(const float4*)(w + u * 128 + v0 + v4i);
        float4 wd4 = *(const float4*)(w + 256 * 128 + v0 + v4i);
        float wv[4] = {fmaf(wd4.x, qu, wv4.x), fmaf(wd4.y, qu, wv4.y),
                       fmaf(wd4.z, qu, wv4.z), fmaf(wd4.w, qu, wv4.w)};
        #pragma unroll
        for (int i = 0; i < 4; i++) {
            __nv_bfloat16 h = __float2bfloat16(wv[i]);
            __nv_bfloat16 l = __float2bfloat16(wv[i] - __bfloat162float(h));
            *(__nv_bfloat16*)(sm + OFF_B_HI + (v4i + i) * B_STRIDE_B + u * 2) = h;
            *(__nv_bfloat16*)(sm + OFF_B_LO + (v4i + i) * B_STRIDE_B + u * 2) = l;
        }
    }
    __syncthreads();

    // ---- GEMM: warp tile = 32 j x 16 v (2 m-tiles x 2 n-tiles), K=128, 3 splits ----
    const int wj = (wid & 3) * 32;          // j block (group g = wid&3)
    const int wv = (wid >> 2) * 16;         // local v block

    float acc[2][2][4];
    #pragma unroll
    for (int mt = 0; mt < 2; mt++)
        #pragma unroll
        for (int n = 0; n < 2; n++)
            #pragma unroll
            for (int c = 0; c < 4; c++) acc[mt][n][c] = 0.f;

    {
        const int lrow  = lid & 15;
        const int lcolb = (lid >> 4) * 16;
        const int bn = lid >> 2;
        const int bk = (lid & 3) * 4;

        const uint32_t a_off[3] = {OFF_A_HI, OFF_A_LO, OFF_A_HI};
        const uint32_t b_off[3] = {OFF_B_HI, OFF_B_HI, OFF_B_LO};
        const uint32_t smb = smem_u32(sm);

        #pragma unroll
        for (int s = 0; s < 3; s++) {
            const uint32_t abase = smb + a_off[s]
                                 + (uint32_t)(wj + lrow) * A_STRIDE_B + lcolb;
            const char* bbase = sm + b_off[s];
            #pragma unroll
            for (int k = 0; k < 8; k++) {
                uint32_t a0[4], a1[4];
                ldmatrix_x4(a0, abase + k * 32);
                ldmatrix_x4(a1, abase + 16 * A_STRIDE_B + k * 32);
                #pragma unroll
                for (int n = 0; n < 2; n++) {
                    const char* bp = bbase + (wv + n * 8 + bn) * B_STRIDE_B + k * 32 + bk;
                    uint32_t b0 = *(const uint32_t*)bp;
                    uint32_t b1 = *(const uint32_t*)(bp + 16);
                    mma_16816(acc[0][n], a0, b0, b1);
                    mma_16816(acc[1][n], a1, b0, b1);
                }
            }
        }
    }

    // ---- Fused epilogue: exp on fragments, weighted sums ----
    {
        const int er = lid >> 2;            // j row within tile
        const int ec = (lid & 3) * 2;       // v pair within tile

        float se[2][2] = {{0.f, 0.f}, {0.f, 0.f}};   // [n][v-pair elem]
        float oo[2][2] = {{0.f, 0.f}, {0.f, 0.f}};

        #pragma unroll
        for (int mt = 0; mt < 2; mt++) {
            int j0 = wj + mt * 16 + er, j8 = j0 + 8;
            #pragma unroll
            for (int n = 0; n < 2; n++) {
                int v = wv + n * 8 + ec;
                float e00 = __expf(acc[mt][n][0]);
                float e01 = __expf(acc[mt][n][1]);
                float e10 = __expf(acc[mt][n][2]);
                float e11 = __expf(acc[mt][n][3]);
                se[n][0] += e00 + e10;
                se[n][1] += e01 + e11;
                oo[n][0] = fmaf(e00, fT[v * FT_STRIDE + j0], oo[n][0]);
                oo[n][0] = fmaf(e10, fT[v * FT_STRIDE + j8], oo[n][0]);
                oo[n][1] = fmaf(e01, fT[(v + 1) * FT_STRIDE + j0], oo[n][1]);
                oo[n][1] = fmaf(e11, fT[(v + 1) * FT_STRIDE + j8], oo[n][1]);
            }
        }

        // reduce over the 8 er-lanes (lid bits 2..4)
        #pragma unroll
        for (int n = 0; n < 2; n++)
            #pragma unroll
            for (int c = 0; c < 2; c++) {
                se[n][c] += __shfl_xor_sync(0xffffffffu, se[n][c], 4);
                se[n][c] += __shfl_xor_sync(0xffffffffu, se[n][c], 8);
                se[n][c] += __shfl_xor_sync(0xffffffffu, se[n][c], 16);
                oo[n][c] += __shfl_xor_sync(0xffffffffu, oo[n][c], 4);
                oo[n][c] += __shfl_xor_sync(0xffffffffu, oo[n][c], 8);
                oo[n][c] += __shfl_xor_sync(0xffffffffu, oo[n][c], 16);
            }

        // lanes 0..3 deposit partials for this warp's j-group g = wid&3
        if (lid < 4) {
            const int g = wid & 3;
            #pragma unroll
            for (int n = 0; n < 2; n++) {
                int v = wv + n * 8 + ec;    // ec = 2*lid here
                red[g * 64 + v]           = se[n][0];
                red[g * 64 + v + 1]       = se[n][1];
                red[256 + g * 64 + v]     = oo[n][0];
                red[256 + g * 64 + v + 1] = oo[n][1];
            }
        }
    }
    __syncthreads();

    // ---- Final: sum 4 j-group partials, divide, store ----
    if (tid < 64) {
        float se = (red[tid] + red[64 + tid]) + (red[128 + tid] + red[192 + tid]);
        float o  = (red[256 + tid] + red[320 + tid]) + (red[384 + tid] + red[448 + tid]);
        out[b * 128 + v0 + tid] = __fdividef(o, se);
    }
}

extern "C" void kernel_launch(void* const* d_in, const int* in_sizes, int n_in,
                              void* d_out, int out_size)
{
    const float* input = (const float*)d_in[0];   // (64,128)
    const float* state = (const float*)d_in[1];   // (64,128,128)
    const float* w     = (const float*)d_in[2];   // (257,128); w[128:256], b unused
    float* out = (float*)d_out;                   // (64,128)

    cudaFuncSetAttribute(rsa_kernel,
                         cudaFuncAttributeMaxDynamicSharedMemorySize, SMEM_BYTES);
    rsa_kernel<<<128, THREADS, SMEM_BYTES>>>(input, state, w, out);
}